// round 8
// baseline (speedup 1.0000x reference)
#include <cuda_runtime.h>
#include <math.h>
#include <stdint.h>

#define NTAG 36
#define SEQ  512
#define HID  512
#define EMB  512
#define G4   2048   // 4*HID
#define NCTA 128
#define NREP 8      // replication factor for h / counters (kills L2 hot lines)
#define HREP 640    // replica stride in floats (2560B -> different slice hash)

// ---------------- device scratch (no allocations allowed) ----------------
__device__ __align__(16) float g_embeds[SEQ * EMB];        // 1 MB
__device__ __align__(16) float g_P[SEQ * G4];              // 4 MB: Wih@x + bih + bhh
__device__ __align__(16) float g_hrep[2][NREP][HREP];      // replicated h (double-buffered)
__device__ __align__(16) float g_c[HID];
__device__ int g_tag_list[NTAG * SEQ];
__device__ int g_tag_cnt[NTAG];
__device__ __align__(128) unsigned g_ctrs[NREP][32];       // 8 counters, one line each

__device__ __forceinline__ float sigmoidf_(float x) {
    return 1.0f / (1.0f + __expf(-x));
}
__device__ __forceinline__ float tanhf_(float x) {
    return 2.0f / (1.0f + __expf(-2.0f * x)) - 1.0f;
}
__device__ __forceinline__ void cp16(uint32_t smem_addr, const void* gptr) {
    asm volatile("cp.async.cg.shared.global [%0], [%1], 16;\n"
                 :: "r"(smem_addr), "l"(gptr));
}
__device__ __forceinline__ unsigned ld_acq_u32(const unsigned* p) {
    unsigned v;
    asm volatile("ld.global.acquire.gpu.b32 %0, [%1];" : "=r"(v) : "l"(p));
    return v;
}
__device__ __forceinline__ void red_rel_add(unsigned* p, unsigned v) {
    asm volatile("red.global.release.gpu.add.u32 [%0], %1;" :: "l"(p), "r"(v) : "memory");
}

// ---------------- init ----------------
__global__ void k_init(const float* __restrict__ h0, const float* __restrict__ c0,
                       const int* __restrict__ tags) {
    int j = threadIdx.x;            // 512 threads
    #pragma unroll
    for (int r = 0; r < NREP; ++r) g_hrep[0][r][j] = h0[j];
    g_c[j] = c0[j];
    if (j < NTAG) g_tag_cnt[j] = 0;
    if (j < NREP) g_ctrs[j][0] = 0;
    __syncthreads();
    int tag = tags[j];
    int pos = atomicAdd(&g_tag_cnt[tag], 1);
    g_tag_list[tag * SEQ + pos] = j;
}

// ---------------- embedding gather ----------------
__global__ void k_embed(const int* __restrict__ x, const float* __restrict__ emb) {
    int t = blockIdx.x;             // grid 512, block 128
    int row = x[t];
    const float4* src = (const float4*)emb + (size_t)row * (EMB / 4);
    float4* dst = (float4*)g_embeds + (size_t)t * (EMB / 4);
    dst[threadIdx.x] = src[threadIdx.x];
}

// ---------------- precompute P[t] = Wih[tag_t] @ x_t + bih + bhh (148us config) ----
__global__ void k_precompute(const float* __restrict__ Wih,
                             const float* __restrict__ bih,
                             const float* __restrict__ bhh) {
    __shared__ float4 Xs[16 * 128];
    __shared__ int ts[16];
    int g   = blockIdx.x;
    int cnt = g_tag_cnt[g];
    int c0  = blockIdx.z * 16;
    if (c0 >= cnt) return;
    int m   = min(16, cnt - c0);
    int tid = threadIdx.x;

    if (tid < 16) ts[tid] = (tid < m) ? g_tag_list[g * SEQ + c0 + tid] : 0;
    __syncthreads();

    #pragma unroll
    for (int it = 0; it < 16; ++it) {
        int i = it * 128 + tid;
        int n = i >> 7, kk = i & 127;
        Xs[i] = (n < m) ? ((const float4*)g_embeds)[(size_t)ts[n] * 128 + kk]
                        : make_float4(0.f, 0.f, 0.f, 0.f);
    }
    __syncthreads();

    int r = blockIdx.y * 128 + tid;
    const float4* wrow = (const float4*)(Wih + ((size_t)g * G4 + r) * EMB);

    float acc[16];
    #pragma unroll
    for (int n = 0; n < 16; ++n) acc[n] = 0.f;

    #pragma unroll 2
    for (int kk = 0; kk < 128; ++kk) {
        float4 w = __ldg(wrow + kk);
        #pragma unroll
        for (int n = 0; n < 16; ++n) {
            float4 xv = Xs[n * 128 + kk];
            acc[n] += w.x * xv.x + w.y * xv.y + w.z * xv.z + w.w * xv.w;
        }
    }

    float bias = bih[g * G4 + r] + bhh[g * G4 + r];
    for (int n = 0; n < m; ++n)
        g_P[(size_t)ts[n] * G4 + r] = acc[n] + bias;
}

// ---------------- persistent recurrent kernel (warp-specialized, replicated sync) ----
// 128 CTAs x 288 threads (9 warps). CTA b owns j in [4b,4b+4).
// warp 0: sync/h/gates. warps 1-8 (idx=w-1): rows {p*512+j,(p+1)*512+j}.
// h + counter replicated 8x; CTA b polls/reads replica b&7; producer writes all 8.
__global__ void __launch_bounds__(288, 1) k_seq(const float* __restrict__ Whh,
                                                const int* __restrict__ tags_g) {
    extern __shared__ char dsm[];
    float*  wsb   = (float*)dsm;                         // [2][8 warps][1024]  64 KB
    float4* hs4   = (float4*)(dsm + 65536);              // h stage, 512 floats
    int*    stags = (int*)  (dsm + 65536 + 2048);        // 512 ints
    float*  sred  = (float*)(dsm + 65536 + 4096);        // 16 floats

    int tid  = threadIdx.x;
    int lane = tid & 31;
    int w    = tid >> 5;                 // 0..8
    int b    = blockIdx.x;
    int rep  = b & (NREP - 1);
    int idx  = w - 1;                    // compute-warp index 0..7 (w>=1)
    int j    = b * 4 + (idx & 3);
    int r0   = ((idx >> 2) * 2) * HID + j;

    for (int i = tid; i < SEQ; i += 288) stags[i] = tags_g[i];
    __syncthreads();

    float c = (tid < 4) ? g_c[b * 4 + tid] : 0.f;

    uint32_t wbase = 0;
    const size_t ROWSTRIDE = (size_t)HID;
    if (w > 0) {
        wbase = (uint32_t)__cvta_generic_to_shared(wsb + idx * 1024);
        #pragma unroll
        for (int s = 0; s < 2; ++s) {
            const float* s0 = Whh + ((size_t)stags[s] * G4 + r0) * ROWSTRIDE;
            const float* s1 = s0 + 512 * ROWSTRIDE;
            uint32_t d = wbase + s * 32768;
            #pragma unroll
            for (int k = 0; k < 4; ++k) {
                cp16(d +        (lane + 32 * k) * 16, s0 + (lane + 32 * k) * 4);
                cp16(d + 2048 + (lane + 32 * k) * 16, s1 + (lane + 32 * k) * 4);
            }
            asm volatile("cp.async.commit_group;\n" ::: "memory");
        }
    }

    float pi = 0.f, pf = 0.f, pg = 0.f, po = 0.f;

    for (int t = 0; t < SEQ; ++t) {
        int slot = t & 1;

        if (w == 0) {
            // P prefetch (lanes 0-3), then immediately poll own counter replica
            if (lane < 4) {
                const float* Pt = g_P + (size_t)t * G4 + b * 4 + lane;
                pi = __ldg(Pt);
                pf = __ldg(Pt + 512);
                pg = __ldg(Pt + 1024);
                po = __ldg(Pt + 1536);
            }
            unsigned target = (unsigned)NCTA * (unsigned)t;
            while (ld_acq_u32(&g_ctrs[rep][0]) < target) { }
            const float4* hg = (const float4*)g_hrep[t & 1][rep];
            hs4[lane]      = __ldcg(hg + lane);
            hs4[lane + 32] = __ldcg(hg + lane + 32);
            hs4[lane + 64] = __ldcg(hg + lane + 64);
            hs4[lane + 96] = __ldcg(hg + lane + 96);
            __syncthreads();   // bar1: h staged
            __syncthreads();   // bar2: sred ready
            if (lane < 4) {
                float gi = sred[2 * lane]     + pi;
                float gf = sred[2 * lane + 1] + pf;
                float gg = sred[8 + 2 * lane] + pg;
                float go = sred[9 + 2 * lane] + po;
                float iv = sigmoidf_(gi);
                float fv = sigmoidf_(gf);
                float gv = tanhf_(gg);
                float ov = sigmoidf_(go);
                c = fv * c + iv * gv;
                float hv = ov * tanhf_(c);
                float h1v = __shfl_sync(0x0000000Fu, hv, 1);
                float h2v = __shfl_sync(0x0000000Fu, hv, 2);
                float h3v = __shfl_sync(0x0000000Fu, hv, 3);
                if (lane == 0) {
                    float4 hq = make_float4(hv, h1v, h2v, h3v);
                    #pragma unroll
                    for (int r = 0; r < NREP; ++r)
                        __stcg((float4*)&g_hrep[(t + 1) & 1][r][b * 4], hq);
                    #pragma unroll
                    for (int r = 0; r < NREP; ++r)
                        red_rel_add(&g_ctrs[r][0], 1u);   // release orders all h stores
                }
            }
        } else {
            // compute warps: weight LDS + refill overlap warp 0's poll
            asm volatile("cp.async.wait_group 1;\n" ::: "memory");
            const float4* wr = (const float4*)(wsb + slot * 8192 + idx * 1024);
            float4 b0 = wr[lane],            b1 = wr[lane + 32];
            float4 b2 = wr[lane + 64],       b3 = wr[lane + 96];
            float4 e0 = wr[128 + lane],      e1 = wr[128 + lane + 32];
            float4 e2 = wr[128 + lane + 64], e3 = wr[128 + lane + 96];

            if (t + 2 < SEQ) {
                const float* s0 = Whh + ((size_t)stags[t + 2] * G4 + r0) * ROWSTRIDE;
                const float* s1 = s0 + 512 * ROWSTRIDE;
                uint32_t d = wbase + slot * 32768;
                #pragma unroll
                for (int k = 0; k < 4; ++k) {
                    cp16(d +        (lane + 32 * k) * 16, s0 + (lane + 32 * k) * 4);
                    cp16(d + 2048 + (lane + 32 * k) * 16, s1 + (lane + 32 * k) * 4);
                }
            }
            asm volatile("cp.async.commit_group;\n" ::: "memory");

            __syncthreads();   // bar1: wait for h in smem

            float4 h0 = hs4[lane];
            float4 h1 = hs4[lane + 32];
            float4 h2 = hs4[lane + 64];
            float4 h3 = hs4[lane + 96];
            float acc0 = b0.x*h0.x + b0.y*h0.y + b0.z*h0.z + b0.w*h0.w
                       + b1.x*h1.x + b1.y*h1.y + b1.z*h1.z + b1.w*h1.w
                       + b2.x*h2.x + b2.y*h2.y + b2.z*h2.z + b2.w*h2.w
                       + b3.x*h3.x + b3.y*h3.y + b3.z*h3.z + b3.w*h3.w;
            float acc1 = e0.x*h0.x + e0.y*h0.y + e0.z*h0.z + e0.w*h0.w
                       + e1.x*h1.x + e1.y*h1.y + e1.z*h1.z + e1.w*h1.w
                       + e2.x*h2.x + e2.y*h2.y + e2.z*h2.z + e2.w*h2.w
                       + e3.x*h3.x + e3.y*h3.y + e3.z*h3.z + e3.w*h3.w;
            #pragma unroll
            for (int off = 16; off; off >>= 1) {
                acc0 += __shfl_down_sync(0xffffffffu, acc0, off);
                acc1 += __shfl_down_sync(0xffffffffu, acc1, off);
            }
            if (lane == 0) { sred[idx * 2] = acc0; sred[idx * 2 + 1] = acc1; }
            __syncthreads();   // bar2: sred published
        }
    }

    if (tid < 4) g_c[b * 4 + tid] = c;
}

// ---------------- final fc + sigmoid + pack outputs ----------------
__global__ void k_final(const float* __restrict__ Wfc, const float* __restrict__ bfc,
                        float* __restrict__ out, int out_size) {
    __shared__ float red[16];
    int tid = threadIdx.x;            // 512 threads
    float hv = g_hrep[0][0][tid];     // after step 511 (even), h lives in buffer 0
    float v = hv * Wfc[tid];
    #pragma unroll
    for (int off = 16; off; off >>= 1) v += __shfl_down_sync(0xffffffffu, v, off);
    if ((tid & 31) == 0) red[tid >> 5] = v;
    __syncthreads();
    if (tid < 16) {
        float s = red[tid];
        #pragma unroll
        for (int off = 8; off; off >>= 1) s += __shfl_down_sync(0x0000ffffu, s, off);
        if (tid == 0 && out_size > 0)
            out[0] = sigmoidf_(s + bfc[0]);
    }
    if (1 + tid < out_size)   out[1 + tid]   = hv;
    if (513 + tid < out_size) out[513 + tid] = g_c[tid];
}

// ---------------- launcher ----------------
extern "C" void kernel_launch(void* const* d_in, const int* in_sizes, int n_in,
                              void* d_out, int out_size) {
    const int*   x    = (const int*)d_in[0];
    const int*   tags = (const int*)d_in[1];
    const float* h0   = (const float*)d_in[2];
    const float* c0   = (const float*)d_in[3];
    const float* emb  = (const float*)d_in[4];
    const float* Wih  = (const float*)d_in[5];
    const float* Whh  = (const float*)d_in[6];
    const float* bih  = (const float*)d_in[7];
    const float* bhh  = (const float*)d_in[8];
    const float* Wfc  = (const float*)d_in[9];
    const float* bfc  = (const float*)d_in[10];
    (void)in_sizes; (void)n_in;

    const int SMEM_SEQ = 65536 + 2048 + 2048 + 128;   // 68.3 KB dynamic
    cudaFuncSetAttribute(k_seq, cudaFuncAttributeMaxDynamicSharedMemorySize, SMEM_SEQ);

    k_init<<<1, 512>>>(h0, c0, tags);
    k_embed<<<512, 128>>>(x, emb);
    k_precompute<<<dim3(NTAG, 16, 32), 128>>>(Wih, bih, bhh);
    k_seq<<<NCTA, 288, SMEM_SEQ>>>(Whh, tags);
    k_final<<<1, 512>>>(Wfc, bfc, (float*)d_out, out_size);
}

// round 10
// speedup vs baseline: 1.4299x; 1.4299x over previous
#include <cuda_runtime.h>
#include <math.h>
#include <stdint.h>

#define NTAG 36
#define SEQ  512
#define HID  512
#define EMB  512
#define G4   2048   // 4*HID
#define NCTA 128
#define NREPC 4     // counter replicas (detect de-contention)

// ---------------- device scratch (no allocations allowed) ----------------
__device__ __align__(16) float g_embeds[SEQ * EMB];        // 1 MB
__device__ __align__(16) float g_P[SEQ * G4];              // 4 MB: Wih@x + bih + bhh
__device__ __align__(16) float g_h[2][HID];
__device__ __align__(16) float g_c[HID];
__device__ int g_tag_list[NTAG * SEQ];
__device__ int g_tag_cnt[NTAG];
__device__ __align__(128) unsigned g_ctrs[NREPC][32];      // 4 counters, one line each

__device__ __forceinline__ float sigmoidf_(float x) {
    return 1.0f / (1.0f + __expf(-x));
}
__device__ __forceinline__ float tanhf_(float x) {
    return 2.0f / (1.0f + __expf(-2.0f * x)) - 1.0f;
}
__device__ __forceinline__ void cp16(uint32_t smem_addr, const void* gptr) {
    asm volatile("cp.async.cg.shared.global [%0], [%1], 16;\n"
                 :: "r"(smem_addr), "l"(gptr));
}
__device__ __forceinline__ unsigned ld_acq_u32(const unsigned* p) {
    unsigned v;
    asm volatile("ld.global.acquire.gpu.b32 %0, [%1];" : "=r"(v) : "l"(p));
    return v;
}
__device__ __forceinline__ void red_rel_add(unsigned* p, unsigned v) {
    asm volatile("red.global.release.gpu.add.u32 [%0], %1;" :: "l"(p), "r"(v) : "memory");
}

// ---------------- init ----------------
__global__ void k_init(const float* __restrict__ h0, const float* __restrict__ c0,
                       const int* __restrict__ tags) {
    int j = threadIdx.x;            // 512 threads
    g_h[0][j] = h0[j];
    g_c[j]    = c0[j];
    if (j < NTAG) g_tag_cnt[j] = 0;
    if (j < NREPC) g_ctrs[j][0] = 0;
    __syncthreads();
    int tag = tags[j];
    int pos = atomicAdd(&g_tag_cnt[tag], 1);
    g_tag_list[tag * SEQ + pos] = j;
}

// ---------------- embedding gather ----------------
__global__ void k_embed(const int* __restrict__ x, const float* __restrict__ emb) {
    int t = blockIdx.x;             // grid 512, block 128
    int row = x[t];
    const float4* src = (const float4*)emb + (size_t)row * (EMB / 4);
    float4* dst = (float4*)g_embeds + (size_t)t * (EMB / 4);
    dst[threadIdx.x] = src[threadIdx.x];
}

// ---------------- precompute P[t] = Wih[tag_t] @ x_t + bih + bhh ----------------
// chunk = 8 timesteps -> ~2x active CTAs vs chunk 16 (latency-bound kernel).
// grid: (36 tags, 16 row-blocks of 128, 64 chunks of 8 timesteps). block 128.
__global__ void k_precompute(const float* __restrict__ Wih,
                             const float* __restrict__ bih,
                             const float* __restrict__ bhh) {
    __shared__ float4 Xs[8 * 128];    // 8 timesteps x 512 floats = 16 KB
    __shared__ int ts[8];
    int g   = blockIdx.x;
    int cnt = g_tag_cnt[g];
    int c0  = blockIdx.z * 8;
    if (c0 >= cnt) return;            // uniform per CTA
    int m   = min(8, cnt - c0);
    int tid = threadIdx.x;

    if (tid < 8) ts[tid] = (tid < m) ? g_tag_list[g * SEQ + c0 + tid] : 0;
    __syncthreads();

    #pragma unroll
    for (int it = 0; it < 8; ++it) {
        int i = it * 128 + tid;
        int n = i >> 7, kk = i & 127;
        Xs[i] = (n < m) ? ((const float4*)g_embeds)[(size_t)ts[n] * 128 + kk]
                        : make_float4(0.f, 0.f, 0.f, 0.f);
    }
    __syncthreads();

    int r = blockIdx.y * 128 + tid;
    const float4* wrow = (const float4*)(Wih + ((size_t)g * G4 + r) * EMB);

    float acc[8];
    #pragma unroll
    for (int n = 0; n < 8; ++n) acc[n] = 0.f;

    #pragma unroll 4
    for (int kk = 0; kk < 128; ++kk) {
        float4 w = __ldg(wrow + kk);
        #pragma unroll
        for (int n = 0; n < 8; ++n) {
            float4 xv = Xs[n * 128 + kk];
            acc[n] += w.x * xv.x + w.y * xv.y + w.z * xv.z + w.w * xv.w;
        }
    }

    float bias = bih[g * G4 + r] + bhh[g * G4 + r];
    for (int n = 0; n < m; ++n)
        g_P[(size_t)ts[n] * G4 + r] = acc[n] + bias;
}

// ---------------- persistent recurrent kernel (R7 base + replicated counters) ----
// 128 CTAs x 288 threads (9 warps). CTA b owns j in [4b,4b+4).
// warp 0: sync/h/gates. warps 1-8 (idx=w-1): rows {p*512+j,(p+1)*512+j}.
// Producer: one STG.128 of h4, then 4x red.release (first drains the store,
// rest are fire-and-forget). Consumer polls ONLY its replica b&3 (32 pollers/line).
__global__ void __launch_bounds__(288, 1) k_seq(const float* __restrict__ Whh,
                                                const int* __restrict__ tags_g) {
    extern __shared__ char dsm[];
    float*  wsb   = (float*)dsm;                         // [2][8 warps][1024]  64 KB
    float4* hs4   = (float4*)(dsm + 65536);              // h stage, 512 floats
    int*    stags = (int*)  (dsm + 65536 + 2048);        // 512 ints
    float*  sred  = (float*)(dsm + 65536 + 4096);        // 16 floats

    int tid  = threadIdx.x;
    int lane = tid & 31;
    int w    = tid >> 5;                 // 0..8
    int b    = blockIdx.x;
    int rep  = b & (NREPC - 1);
    int idx  = w - 1;                    // compute-warp index 0..7 (w>=1)
    int j    = b * 4 + (idx & 3);
    int r0   = ((idx >> 2) * 2) * HID + j;

    for (int i = tid; i < SEQ; i += 288) stags[i] = tags_g[i];
    __syncthreads();

    float c = (tid < 4) ? g_c[b * 4 + tid] : 0.f;

    uint32_t wbase = 0;
    const size_t ROWSTRIDE = (size_t)HID;
    if (w > 0) {
        wbase = (uint32_t)__cvta_generic_to_shared(wsb + idx * 1024);
        #pragma unroll
        for (int s = 0; s < 2; ++s) {
            const float* s0 = Whh + ((size_t)stags[s] * G4 + r0) * ROWSTRIDE;
            const float* s1 = s0 + 512 * ROWSTRIDE;
            uint32_t d = wbase + s * 32768;
            #pragma unroll
            for (int k = 0; k < 4; ++k) {
                cp16(d +        (lane + 32 * k) * 16, s0 + (lane + 32 * k) * 4);
                cp16(d + 2048 + (lane + 32 * k) * 16, s1 + (lane + 32 * k) * 4);
            }
            asm volatile("cp.async.commit_group;\n" ::: "memory");
        }
    }

    float pi = 0.f, pf = 0.f, pg = 0.f, po = 0.f;

    for (int t = 0; t < SEQ; ++t) {
        int slot = t & 1;

        if (w == 0) {
            // P prefetch (lanes 0-3), then immediately poll own counter replica
            if (lane < 4) {
                const float* Pt = g_P + (size_t)t * G4 + b * 4 + lane;
                pi = __ldg(Pt);
                pf = __ldg(Pt + 512);
                pg = __ldg(Pt + 1024);
                po = __ldg(Pt + 1536);
            }
            unsigned target = (unsigned)NCTA * (unsigned)t;
            while (ld_acq_u32(&g_ctrs[rep][0]) < target) { }
            const float4* hg = (const float4*)g_h[t & 1];
            hs4[lane]      = __ldcg(hg + lane);
            hs4[lane + 32] = __ldcg(hg + lane + 32);
            hs4[lane + 64] = __ldcg(hg + lane + 64);
            hs4[lane + 96] = __ldcg(hg + lane + 96);
            __syncthreads();   // bar1: h staged
            __syncthreads();   // bar2: sred ready
            if (lane < 4) {
                float gi = sred[2 * lane]     + pi;
                float gf = sred[2 * lane + 1] + pf;
                float gg = sred[8 + 2 * lane] + pg;
                float go = sred[9 + 2 * lane] + po;
                float iv = sigmoidf_(gi);
                float fv = sigmoidf_(gf);
                float gv = tanhf_(gg);
                float ov = sigmoidf_(go);
                c = fv * c + iv * gv;
                float hv = ov * tanhf_(c);
                float h1v = __shfl_sync(0x0000000Fu, hv, 1);
                float h2v = __shfl_sync(0x0000000Fu, hv, 2);
                float h3v = __shfl_sync(0x0000000Fu, hv, 3);
                if (lane == 0) {
                    float4 hq = make_float4(hv, h1v, h2v, h3v);
                    *(float4*)&g_h[(t + 1) & 1][b * 4] = hq;   // one 16B store
                    #pragma unroll
                    for (int r = 0; r < NREPC; ++r)
                        red_rel_add(&g_ctrs[r][0], 1u);        // each release orders the store
                }
            }
        } else {
            // compute warps: weight LDS + refill overlap warp 0's poll
            asm volatile("cp.async.wait_group 1;\n" ::: "memory");
            const float4* wr = (const float4*)(wsb + slot * 8192 + idx * 1024);
            float4 b0 = wr[lane],            b1 = wr[lane + 32];
            float4 b2 = wr[lane + 64],       b3 = wr[lane + 96];
            float4 e0 = wr[128 + lane],      e1 = wr[128 + lane + 32];
            float4 e2 = wr[128 + lane + 64], e3 = wr[128 + lane + 96];

            if (t + 2 < SEQ) {
                const float* s0 = Whh + ((size_t)stags[t + 2] * G4 + r0) * ROWSTRIDE;
                const float* s1 = s0 + 512 * ROWSTRIDE;
                uint32_t d = wbase + slot * 32768;
                #pragma unroll
                for (int k = 0; k < 4; ++k) {
                    cp16(d +        (lane + 32 * k) * 16, s0 + (lane + 32 * k) * 4);
                    cp16(d + 2048 + (lane + 32 * k) * 16, s1 + (lane + 32 * k) * 4);
                }
            }
            asm volatile("cp.async.commit_group;\n" ::: "memory");

            __syncthreads();   // bar1: wait for h in smem

            float4 h0 = hs4[lane];
            float4 h1 = hs4[lane + 32];
            float4 h2 = hs4[lane + 64];
            float4 h3 = hs4[lane + 96];
            float acc0 = b0.x*h0.x + b0.y*h0.y + b0.z*h0.z + b0.w*h0.w
                       + b1.x*h1.x + b1.y*h1.y + b1.z*h1.z + b1.w*h1.w
                       + b2.x*h2.x + b2.y*h2.y + b2.z*h2.z + b2.w*h2.w
                       + b3.x*h3.x + b3.y*h3.y + b3.z*h3.z + b3.w*h3.w;
            float acc1 = e0.x*h0.x + e0.y*h0.y + e0.z*h0.z + e0.w*h0.w
                       + e1.x*h1.x + e1.y*h1.y + e1.z*h1.z + e1.w*h1.w
                       + e2.x*h2.x + e2.y*h2.y + e2.z*h2.z + e2.w*h2.w
                       + e3.x*h3.x + e3.y*h3.y + e3.z*h3.z + e3.w*h3.w;
            #pragma unroll
            for (int off = 16; off; off >>= 1) {
                acc0 += __shfl_down_sync(0xffffffffu, acc0, off);
                acc1 += __shfl_down_sync(0xffffffffu, acc1, off);
            }
            if (lane == 0) { sred[idx * 2] = acc0; sred[idx * 2 + 1] = acc1; }
            __syncthreads();   // bar2: sred published
        }
    }

    if (tid < 4) g_c[b * 4 + tid] = c;
}

// ---------------- final fc + sigmoid + pack outputs ----------------
__global__ void k_final(const float* __restrict__ Wfc, const float* __restrict__ bfc,
                        float* __restrict__ out, int out_size) {
    __shared__ float red[16];
    int tid = threadIdx.x;            // 512 threads
    float hv = g_h[0][tid];           // after step 511, h lives in buffer 0
    float v = hv * Wfc[tid];
    #pragma unroll
    for (int off = 16; off; off >>= 1) v += __shfl_down_sync(0xffffffffu, v, off);
    if ((tid & 31) == 0) red[tid >> 5] = v;
    __syncthreads();
    if (tid < 16) {
        float s = red[tid];
        #pragma unroll
        for (int off = 8; off; off >>= 1) s += __shfl_down_sync(0x0000ffffu, s, off);
        if (tid == 0 && out_size > 0)
            out[0] = sigmoidf_(s + bfc[0]);
    }
    if (1 + tid < out_size)   out[1 + tid]   = hv;
    if (513 + tid < out_size) out[513 + tid] = g_c[tid];
}

// ---------------- launcher ----------------
extern "C" void kernel_launch(void* const* d_in, const int* in_sizes, int n_in,
                              void* d_out, int out_size) {
    const int*   x    = (const int*)d_in[0];
    const int*   tags = (const int*)d_in[1];
    const float* h0   = (const float*)d_in[2];
    const float* c0   = (const float*)d_in[3];
    const float* emb  = (const float*)d_in[4];
    const float* Wih  = (const float*)d_in[5];
    const float* Whh  = (const float*)d_in[6];
    const float* bih  = (const float*)d_in[7];
    const float* bhh  = (const float*)d_in[8];
    const float* Wfc  = (const float*)d_in[9];
    const float* bfc  = (const float*)d_in[10];
    (void)in_sizes; (void)n_in;

    const int SMEM_SEQ = 65536 + 2048 + 2048 + 128;   // 68.3 KB dynamic
    cudaFuncSetAttribute(k_seq, cudaFuncAttributeMaxDynamicSharedMemorySize, SMEM_SEQ);

    k_init<<<1, 512>>>(h0, c0, tags);
    k_embed<<<512, 128>>>(x, emb);
    k_precompute<<<dim3(NTAG, 16, 64), 128>>>(Wih, bih, bhh);
    k_seq<<<NCTA, 288, SMEM_SEQ>>>(Whh, tags);
    k_final<<<1, 512>>>(Wfc, bfc, (float*)d_out, out_size);
}

// round 11
// speedup vs baseline: 2.1453x; 1.5003x over previous
#include <cuda_runtime.h>
#include <math.h>
#include <stdint.h>

#define NTAG 36
#define SEQ  512
#define HID  512
#define EMB  512
#define G4   2048   // 4*HID
#define NCTA 128

// ---------------- device scratch (no allocations allowed) ----------------
__device__ __align__(16) float g_embeds[SEQ * EMB];        // 1 MB
__device__ __align__(16) float g_P[SEQ * G4];              // 4 MB: Wih@x + bih + bhh
__device__ __align__(16) float g_h[2][HID];
__device__ __align__(16) float g_c[HID];
__device__ int g_tag_list[NTAG * SEQ];
__device__ int g_tag_cnt[NTAG];
__device__ __align__(128) unsigned g_ctr;   // cumulative arrival counter

__device__ __forceinline__ float sigmoidf_(float x) {
    return 1.0f / (1.0f + __expf(-x));
}
__device__ __forceinline__ float tanhf_(float x) {
    return 2.0f / (1.0f + __expf(-2.0f * x)) - 1.0f;
}
__device__ __forceinline__ void cp16(uint32_t smem_addr, const void* gptr) {
    asm volatile("cp.async.cg.shared.global [%0], [%1], 16;\n"
                 :: "r"(smem_addr), "l"(gptr));
}
__device__ __forceinline__ unsigned ld_acq_u32(const unsigned* p) {
    unsigned v;
    asm volatile("ld.global.acquire.gpu.b32 %0, [%1];" : "=r"(v) : "l"(p));
    return v;
}
__device__ __forceinline__ void red_rel_add(unsigned* p, unsigned v) {
    asm volatile("red.global.release.gpu.add.u32 [%0], %1;" :: "l"(p), "r"(v) : "memory");
}

// ---------------- init ----------------
__global__ void k_init(const float* __restrict__ h0, const float* __restrict__ c0,
                       const int* __restrict__ tags) {
    int j = threadIdx.x;            // 512 threads
    g_h[0][j] = h0[j];
    g_c[j]    = c0[j];
    if (j < NTAG) g_tag_cnt[j] = 0;
    if (j == 0)   g_ctr = 0;
    __syncthreads();
    int tag = tags[j];
    int pos = atomicAdd(&g_tag_cnt[tag], 1);
    g_tag_list[tag * SEQ + pos] = j;
}

// ---------------- embedding gather ----------------
__global__ void k_embed(const int* __restrict__ x, const float* __restrict__ emb) {
    int t = blockIdx.x;             // grid 512, block 128
    int row = x[t];
    const float4* src = (const float4*)emb + (size_t)row * (EMB / 4);
    float4* dst = (float4*)g_embeds + (size_t)t * (EMB / 4);
    dst[threadIdx.x] = src[threadIdx.x];
}

// ---------------- precompute P[t] = Wih[tag_t] @ x_t + bih + bhh (148us config) ----
__global__ void k_precompute(const float* __restrict__ Wih,
                             const float* __restrict__ bih,
                             const float* __restrict__ bhh) {
    __shared__ float4 Xs[16 * 128];
    __shared__ int ts[16];
    int g   = blockIdx.x;
    int cnt = g_tag_cnt[g];
    int c0  = blockIdx.z * 16;
    if (c0 >= cnt) return;
    int m   = min(16, cnt - c0);
    int tid = threadIdx.x;

    if (tid < 16) ts[tid] = (tid < m) ? g_tag_list[g * SEQ + c0 + tid] : 0;
    __syncthreads();

    #pragma unroll
    for (int it = 0; it < 16; ++it) {
        int i = it * 128 + tid;
        int n = i >> 7, kk = i & 127;
        Xs[i] = (n < m) ? ((const float4*)g_embeds)[(size_t)ts[n] * 128 + kk]
                        : make_float4(0.f, 0.f, 0.f, 0.f);
    }
    __syncthreads();

    int r = blockIdx.y * 128 + tid;
    const float4* wrow = (const float4*)(Wih + ((size_t)g * G4 + r) * EMB);

    float acc[16];
    #pragma unroll
    for (int n = 0; n < 16; ++n) acc[n] = 0.f;

    #pragma unroll 2
    for (int kk = 0; kk < 128; ++kk) {
        float4 w = __ldg(wrow + kk);
        #pragma unroll
        for (int n = 0; n < 16; ++n) {
            float4 xv = Xs[n * 128 + kk];
            acc[n] += w.x * xv.x + w.y * xv.y + w.z * xv.z + w.w * xv.w;
        }
    }

    float bias = bih[g * G4 + r] + bhh[g * G4 + r];
    for (int n = 0; n < m; ++n)
        g_P[(size_t)ts[n] * G4 + r] = acc[n] + bias;
}

// ---------------- persistent recurrent kernel (R7 base + poll backoff) ----------
// 128 CTAs x 288 threads (9 warps). CTA b owns j in [4b,4b+4).
// warp 0: sync/h/gates. warps 1-8 (idx=w-1): rows {p*512+j,(p+1)*512+j}.
// Sync: one STG.128 + one red.release per CTA per step; ONE poller per CTA with
// nanosleep backoff so the counter line never saturates with poll traffic.
__global__ void __launch_bounds__(288, 1) k_seq(const float* __restrict__ Whh,
                                                const int* __restrict__ tags_g) {
    extern __shared__ char dsm[];
    float*  wsb   = (float*)dsm;                         // [2][8 warps][1024]  64 KB
    float4* hs4   = (float4*)(dsm + 65536);              // h stage, 512 floats
    int*    stags = (int*)  (dsm + 65536 + 2048);        // 512 ints
    float*  sred  = (float*)(dsm + 65536 + 4096);        // 16 floats

    int tid  = threadIdx.x;
    int lane = tid & 31;
    int w    = tid >> 5;                 // 0..8
    int b    = blockIdx.x;
    int idx  = w - 1;                    // compute-warp index 0..7 (w>=1)
    int j    = b * 4 + (idx & 3);
    int r0   = ((idx >> 2) * 2) * HID + j;

    for (int i = tid; i < SEQ; i += 288) stags[i] = tags_g[i];
    __syncthreads();

    float c = (tid < 4) ? g_c[b * 4 + tid] : 0.f;

    uint32_t wbase = 0;
    const size_t ROWSTRIDE = (size_t)HID;
    if (w > 0) {
        wbase = (uint32_t)__cvta_generic_to_shared(wsb + idx * 1024);
        #pragma unroll
        for (int s = 0; s < 2; ++s) {
            const float* s0 = Whh + ((size_t)stags[s] * G4 + r0) * ROWSTRIDE;
            const float* s1 = s0 + 512 * ROWSTRIDE;
            uint32_t d = wbase + s * 32768;
            #pragma unroll
            for (int k = 0; k < 4; ++k) {
                cp16(d +        (lane + 32 * k) * 16, s0 + (lane + 32 * k) * 4);
                cp16(d + 2048 + (lane + 32 * k) * 16, s1 + (lane + 32 * k) * 4);
            }
            asm volatile("cp.async.commit_group;\n" ::: "memory");
        }
    }

    float pi = 0.f, pf = 0.f, pg = 0.f, po = 0.f;

    for (int t = 0; t < SEQ; ++t) {
        int slot = t & 1;

        if (w == 0) {
            // P prefetch (lanes 0-3), then poll with backoff — fast path first
            if (lane < 4) {
                const float* Pt = g_P + (size_t)t * G4 + b * 4 + lane;
                pi = __ldg(Pt);
                pf = __ldg(Pt + 512);
                pg = __ldg(Pt + 1024);
                po = __ldg(Pt + 1536);
            }
            unsigned target = (unsigned)NCTA * (unsigned)t;
            if (ld_acq_u32(&g_ctr) < target) {
                do {
                    __nanosleep(200);       // throttle: keep counter line unsaturated
                } while (ld_acq_u32(&g_ctr) < target);
            }
            const float4* hg = (const float4*)g_h[t & 1];
            hs4[lane]      = __ldcg(hg + lane);
            hs4[lane + 32] = __ldcg(hg + lane + 32);
            hs4[lane + 64] = __ldcg(hg + lane + 64);
            hs4[lane + 96] = __ldcg(hg + lane + 96);
            __syncthreads();   // bar1: h staged
            __syncthreads();   // bar2: sred ready
            if (lane < 4) {
                float gi = sred[2 * lane]     + pi;
                float gf = sred[2 * lane + 1] + pf;
                float gg = sred[8 + 2 * lane] + pg;
                float go = sred[9 + 2 * lane] + po;
                float iv = sigmoidf_(gi);
                float fv = sigmoidf_(gf);
                float gv = tanhf_(gg);
                float ov = sigmoidf_(go);
                c = fv * c + iv * gv;
                float hv = ov * tanhf_(c);
                float h1v = __shfl_sync(0x0000000Fu, hv, 1);
                float h2v = __shfl_sync(0x0000000Fu, hv, 2);
                float h3v = __shfl_sync(0x0000000Fu, hv, 3);
                if (lane == 0) {
                    float4 hq = make_float4(hv, h1v, h2v, h3v);
                    *(float4*)&g_h[(t + 1) & 1][b * 4] = hq;   // one 16B store
                    red_rel_add(&g_ctr, 1u);                   // release orders it
                }
            }
        } else {
            // compute warps: weight LDS + refill overlap warp 0's poll
            asm volatile("cp.async.wait_group 1;\n" ::: "memory");
            const float4* wr = (const float4*)(wsb + slot * 8192 + idx * 1024);
            float4 b0 = wr[lane],            b1 = wr[lane + 32];
            float4 b2 = wr[lane + 64],       b3 = wr[lane + 96];
            float4 e0 = wr[128 + lane],      e1 = wr[128 + lane + 32];
            float4 e2 = wr[128 + lane + 64], e3 = wr[128 + lane + 96];

            if (t + 2 < SEQ) {
                const float* s0 = Whh + ((size_t)stags[t + 2] * G4 + r0) * ROWSTRIDE;
                const float* s1 = s0 + 512 * ROWSTRIDE;
                uint32_t d = wbase + slot * 32768;
                #pragma unroll
                for (int k = 0; k < 4; ++k) {
                    cp16(d +        (lane + 32 * k) * 16, s0 + (lane + 32 * k) * 4);
                    cp16(d + 2048 + (lane + 32 * k) * 16, s1 + (lane + 32 * k) * 4);
                }
            }
            asm volatile("cp.async.commit_group;\n" ::: "memory");

            __syncthreads();   // bar1: wait for h in smem

            float4 h0 = hs4[lane];
            float4 h1 = hs4[lane + 32];
            float4 h2 = hs4[lane + 64];
            float4 h3 = hs4[lane + 96];
            float acc0 = b0.x*h0.x + b0.y*h0.y + b0.z*h0.z + b0.w*h0.w
                       + b1.x*h1.x + b1.y*h1.y + b1.z*h1.z + b1.w*h1.w
                       + b2.x*h2.x + b2.y*h2.y + b2.z*h2.z + b2.w*h2.w
                       + b3.x*h3.x + b3.y*h3.y + b3.z*h3.z + b3.w*h3.w;
            float acc1 = e0.x*h0.x + e0.y*h0.y + e0.z*h0.z + e0.w*h0.w
                       + e1.x*h1.x + e1.y*h1.y + e1.z*h1.z + e1.w*h1.w
                       + e2.x*h2.x + e2.y*h2.y + e2.z*h2.z + e2.w*h2.w
                       + e3.x*h3.x + e3.y*h3.y + e3.z*h3.z + e3.w*h3.w;
            #pragma unroll
            for (int off = 16; off; off >>= 1) {
                acc0 += __shfl_down_sync(0xffffffffu, acc0, off);
                acc1 += __shfl_down_sync(0xffffffffu, acc1, off);
            }
            if (lane == 0) { sred[idx * 2] = acc0; sred[idx * 2 + 1] = acc1; }
            __syncthreads();   // bar2: sred published
        }
    }

    if (tid < 4) g_c[b * 4 + tid] = c;
}

// ---------------- final fc + sigmoid + pack outputs ----------------
__global__ void k_final(const float* __restrict__ Wfc, const float* __restrict__ bfc,
                        float* __restrict__ out, int out_size) {
    __shared__ float red[16];
    int tid = threadIdx.x;            // 512 threads
    float hv = g_h[0][tid];           // after step 511, h lives in buffer 0
    float v = hv * Wfc[tid];
    #pragma unroll
    for (int off = 16; off; off >>= 1) v += __shfl_down_sync(0xffffffffu, v, off);
    if ((tid & 31) == 0) red[tid >> 5] = v;
    __syncthreads();
    if (tid < 16) {
        float s = red[tid];
        #pragma unroll
        for (int off = 8; off; off >>= 1) s += __shfl_down_sync(0x0000ffffu, s, off);
        if (tid == 0 && out_size > 0)
            out[0] = sigmoidf_(s + bfc[0]);
    }
    if (1 + tid < out_size)   out[1 + tid]   = hv;
    if (513 + tid < out_size) out[513 + tid] = g_c[tid];
}

// ---------------- launcher ----------------
extern "C" void kernel_launch(void* const* d_in, const int* in_sizes, int n_in,
                              void* d_out, int out_size) {
    const int*   x    = (const int*)d_in[0];
    const int*   tags = (const int*)d_in[1];
    const float* h0   = (const float*)d_in[2];
    const float* c0   = (const float*)d_in[3];
    const float* emb  = (const float*)d_in[4];
    const float* Wih  = (const float*)d_in[5];
    const float* Whh  = (const float*)d_in[6];
    const float* bih  = (const float*)d_in[7];
    const float* bhh  = (const float*)d_in[8];
    const float* Wfc  = (const float*)d_in[9];
    const float* bfc  = (const float*)d_in[10];
    (void)in_sizes; (void)n_in;

    const int SMEM_SEQ = 65536 + 2048 + 2048 + 128;   // 68.3 KB dynamic
    cudaFuncSetAttribute(k_seq, cudaFuncAttributeMaxDynamicSharedMemorySize, SMEM_SEQ);

    k_init<<<1, 512>>>(h0, c0, tags);
    k_embed<<<512, 128>>>(x, emb);
    k_precompute<<<dim3(NTAG, 16, 32), 128>>>(Wih, bih, bhh);
    k_seq<<<NCTA, 288, SMEM_SEQ>>>(Whh, tags);
    k_final<<<1, 512>>>(Wfc, bfc, (float*)d_out, out_size);
}